// round 17
// baseline (speedup 1.0000x reference)
#include <cuda_runtime.h>
#include <math.h>

#define NUM_BINS    128
#define NUM_NETS    100000
#define NUM_NODES   200000
#define NUM_MOVABLE 180000
#define NUM_PINS    400000
#define NREP        8               // replicas of each diff array

#define SB       7.8125f            // bin size (1000/128), exact in fp32
#define INV_SB   0.128f             // approx 1/SB; corrected in bin_of
#define BIN_AREA 61.03515625f       // SB*SB, exact
#define CXU (1.0f / (BIN_AREA * 1.5f))
#define CYU (1.0f / (BIN_AREA * 1.4f))

#define GRID 296                    // 2 blocks/SM on 148+ SMs: all wave-1 resident
#define BLK  512
#define NTH  (GRID * BLK)

// Scratch. All zero at load; scan phase re-zeroes each invocation.
// g_de: even-y pairs, slot k = logical bin k.
// g_do: odd-y pairs stored one slot early (slot k = logical bin k+1), so a
//       pair starting at odd y lands at an even, 16B-aligned slot.
__device__ __align__(16) float2 g_de[NREP][NUM_BINS * NUM_BINS];
__device__ __align__(16) float2 g_do[NREP][NUM_BINS * NUM_BINS];
__device__ float2 g_pp[NUM_PINS];                            // interleaved pin coords
__device__ float2 g_pref[NUM_BINS * NUM_BINS];               // after y-prefix
__device__ __align__(16) float g_util[NUM_BINS * NUM_BINS];  // final util [x*128+y]
__device__ int    g_bar;                                     // grid barrier counter

__device__ __forceinline__ int bin_of(float v) {
    int b = (int)(v * INV_SB);
    b = max(0, min(NUM_BINS - 1, b));
    if (v < (float)b * SB) b--;
    else if (v >= (float)(b + 1) * SB) b++;
    return max(0, min(NUM_BINS - 1, b));
}

__device__ __forceinline__ void red_add4(float2* addr, float a0, float b0,
                                         float a1, float b1) {
    asm volatile("red.global.add.v4.f32 [%0], {%1, %2, %3, %4};"
                 :: "l"(addr), "f"(a0), "f"(b0), "f"(a1), "f"(b1) : "memory");
}

__device__ __forceinline__ void grid_bar(int target) {
    __syncthreads();
    __threadfence();
    if (threadIdx.x == 0) {
        atomicAdd(&g_bar, 1);
        while (atomicAdd(&g_bar, 0) < target) __nanosleep(32);
    }
    __syncthreads();
    __threadfence();
}

// One v4 RED covering logical bins (y, y+1) of x-row `row`, replica `rep`.
__device__ __forceinline__ void emit_pair(int rep, int row, int y,
                                          float a0, float b0, float a1, float b1) {
    if ((y & 1) == 0) {
        red_add4(&g_de[rep][row * NUM_BINS + y], a0, b0, a1, b1);
    } else {
        red_add4(&g_do[rep][row * NUM_BINS + (y - 1)], a0, b0, a1, b1);
    }
}

// Quad-reduced bbox -> this lane's 2 v4 updates; lane q owns x-row q.
__device__ __forceinline__ void process_net(int n, int q, float w,
                                            float xmn, float xmx,
                                            float ymn, float ymx) {
    float dx = xmx - xmn, dy = ymx - ymn;
    float cx = (dy > 0.f) ? (w / dy) : 0.f;   // scales map_x
    float cy = (dx > 0.f) ? (w / dx) : 0.f;   // scales map_y
    if (cx == 0.f && cy == 0.f) return;       // also catches empty nets (inf bbox)

    int x0 = bin_of(xmn), x1 = bin_of(xmx);
    int y0 = bin_of(ymn), y1 = bin_of(ymx);

    float v0x = (float)(x0 + 1) * SB - xmn;
    float v1x = xmx - (float)x1 * SB;
    float v0y = (float)(y0 + 1) * SB - ymn;
    float v1y = ymx - (float)y1 * SB;

    float yv0 = v0y, yv1 = SB - v0y, yv2 = v1y - SB, yv3 = -v1y;

    int   xp   = ((q & 2) ? x1 : x0) + (q & 1);
    float base = (q & 2) ? (v1x - SB) : v0x;
    float alt  = (q & 2) ? (-v1x)     : (SB - v0x);
    float xv   = (q & 1) ? alt : base;

    if (xp < NUM_BINS) {
        int rep = n & (NREP - 1);
        float a = xv * cx, b = xv * cy;
        emit_pair(rep, xp, y0, a * yv0, b * yv0, a * yv1, b * yv1);
        emit_pair(rep, xp, y1, a * yv2, b * yv2, a * yv3, b * yv3);
    }
}

// Single fused persistent kernel: pin-interleave -> nets -> row scan ->
// col scan + util -> nodes, separated by counter grid-barriers.
__global__ void __launch_bounds__(BLK, 2)
fused_kernel(const float* __restrict__ pos,
             const float* __restrict__ pin_pos,
             const float* __restrict__ nszx,
             const float* __restrict__ nszy,
             const float* __restrict__ net_weights,
             const int*   __restrict__ netpin_start,
             const int*   __restrict__ flat_netpin,
             float* __restrict__ out) {
    int tid = threadIdx.x, bid = blockIdx.x;
    int gid0 = bid * BLK + tid;

    // ---- Phase P: interleave pin coords (coalesced) ----
    for (int i = gid0; i < NUM_PINS; i += NTH)
        g_pp[i] = make_float2(__ldg(pin_pos + i), __ldg(pin_pos + i + NUM_PINS));
    grid_bar(GRID);

    // ---- Phase A: nets (quad of lanes per net, two nets per quad-task pair) ----
    // 200,000 quad-tasks; NTH=151,552; all strides & bounds multiples of 32,
    // so warps never split across the loop bound (shfl-safe).
    for (int g = gid0; g < NUM_NETS * 2; g += NTH) {
        int pair = g >> 2;
        int q    = g & 3;
        int n0   = pair * 2, n1 = n0 + 1;

        int s0 = __ldg(netpin_start + n0);
        int e0 = __ldg(netpin_start + n0 + 1);
        int s1 = __ldg(netpin_start + n1);
        int e1 = __ldg(netpin_start + n1 + 1);

        float xmn0 = 3.4e38f, xmx0 = -3.4e38f, ymn0 = 3.4e38f, ymx0 = -3.4e38f;
        float xmn1 = 3.4e38f, xmx1 = -3.4e38f, ymn1 = 3.4e38f, ymx1 = -3.4e38f;

        if ((e0 - s0 == 4) && (e1 - s1 == 4)) {   // hot path for this dataset
            int p0 = __ldg(flat_netpin + s0 + q);
            int p1 = __ldg(flat_netpin + s1 + q);
            float2 c0 = g_pp[p0];
            float2 c1 = g_pp[p1];
            xmn0 = c0.x; xmx0 = c0.x; ymn0 = c0.y; ymx0 = c0.y;
            xmn1 = c1.x; xmx1 = c1.x; ymn1 = c1.y; ymx1 = c1.y;
        } else {                                   // general fallback
            for (int i = s0 + q; i < e0; i += 4) {
                float2 c = g_pp[__ldg(flat_netpin + i)];
                xmn0 = fminf(xmn0, c.x); xmx0 = fmaxf(xmx0, c.x);
                ymn0 = fminf(ymn0, c.y); ymx0 = fmaxf(ymx0, c.y);
            }
            for (int i = s1 + q; i < e1; i += 4) {
                float2 c = g_pp[__ldg(flat_netpin + i)];
                xmn1 = fminf(xmn1, c.x); xmx1 = fmaxf(xmx1, c.x);
                ymn1 = fminf(ymn1, c.y); ymx1 = fmaxf(ymx1, c.y);
            }
        }

        #pragma unroll
        for (int o = 1; o <= 2; o <<= 1) {
            xmn0 = fminf(xmn0, __shfl_xor_sync(0xffffffffu, xmn0, o));
            xmx0 = fmaxf(xmx0, __shfl_xor_sync(0xffffffffu, xmx0, o));
            ymn0 = fminf(ymn0, __shfl_xor_sync(0xffffffffu, ymn0, o));
            ymx0 = fmaxf(ymx0, __shfl_xor_sync(0xffffffffu, ymx0, o));
            xmn1 = fminf(xmn1, __shfl_xor_sync(0xffffffffu, xmn1, o));
            xmx1 = fmaxf(xmx1, __shfl_xor_sync(0xffffffffu, xmx1, o));
            ymn1 = fminf(ymn1, __shfl_xor_sync(0xffffffffu, ymn1, o));
            ymx1 = fmaxf(ymx1, __shfl_xor_sync(0xffffffffu, ymx1, o));
        }

        float w0 = __ldg(net_weights + n0);
        float w1 = __ldg(net_weights + n1);

        process_net(n0, q, w0, xmn0, xmx0, ymn0, ymx0);
        process_net(n1, q, w1, xmn1, xmx1, ymn1, ymx1);
    }
    grid_bar(2 * GRID);

    // ---- Phase B: row scans. Blocks 0-31, each block does 4 rows (one per
    // 128-thread group). Front-batched MLP-16 replica loads absorb the RMW
    // drain; zero what was read; odd-phase shift via shfl + smem seams.
    __shared__ float2 wsum[4][4], wdo[4][4];
    if (bid < 32) {
        int grp  = tid >> 7;          // 0..3: row group
        int t    = tid & 127;         // bin within row
        int b    = bid * 4 + grp;     // row (= x index)
        int lane = tid & 31;
        int wir  = (tid >> 5) & 3;    // warp-in-row-group
        int idx  = b * NUM_BINS + t;

        float2 de[NREP], dd[NREP];
        #pragma unroll
        for (int r = 0; r < NREP; r++) de[r] = g_de[r][idx];
        #pragma unroll
        for (int r = 0; r < NREP; r++) dd[r] = g_do[r][idx];

        float2 v  = make_float2(0.f, 0.f);
        float2 vo = make_float2(0.f, 0.f);
        #pragma unroll
        for (int r = 0; r < NREP; r++) {
            v.x  += de[r].x;  v.y  += de[r].y;
            vo.x += dd[r].x;  vo.y += dd[r].y;
        }
        #pragma unroll
        for (int r = 0; r < NREP; r++) {
            g_de[r][idx] = make_float2(0.f, 0.f);
            g_do[r][idx] = make_float2(0.f, 0.f);
        }

        // logical bin t = de_sum(t) + do_sum(t-1)
        float sx = __shfl_up_sync(0xffffffffu, vo.x, 1);
        float sy = __shfl_up_sync(0xffffffffu, vo.y, 1);
        if (lane == 31) wdo[grp][wir] = vo;
        __syncthreads();
        if (lane == 0) {
            if (wir > 0) { sx = wdo[grp][wir - 1].x; sy = wdo[grp][wir - 1].y; }
            else         { sx = 0.f;                 sy = 0.f; }
        }
        v.x += sx; v.y += sy;

        // 128-wide inclusive scan within the row group
        #pragma unroll
        for (int o = 1; o < 32; o <<= 1) {
            float ax = __shfl_up_sync(0xffffffffu, v.x, o);
            float ay = __shfl_up_sync(0xffffffffu, v.y, o);
            if (lane >= o) { v.x += ax; v.y += ay; }
        }
        if (lane == 31) wsum[grp][wir] = v;
        __syncthreads();
        #pragma unroll
        for (int k = 0; k < 3; k++)
            if (wir > k) { v.x += wsum[grp][k].x; v.y += wsum[grp][k].y; }
        g_pref[idx] = v;
    }
    grid_bar(3 * GRID);

    // ---- Phase C: col scans + util. Blocks 0-31, 4 columns per block. ----
    if (bid < 32) {
        int grp  = tid >> 7;
        int t    = tid & 127;         // x index along the column
        int c    = bid * 4 + grp;     // column (= y index)
        int lane = tid & 31;
        int wir  = (tid >> 5) & 3;

        float2 v;
        {
            const float2* p = g_pref + t * NUM_BINS + c;
            asm volatile("ld.global.cg.v2.f32 {%0, %1}, [%2];"
                         : "=f"(v.x), "=f"(v.y) : "l"(p));
        }
        __syncthreads();              // wsum reuse safe
        #pragma unroll
        for (int o = 1; o < 32; o <<= 1) {
            float ax = __shfl_up_sync(0xffffffffu, v.x, o);
            float ay = __shfl_up_sync(0xffffffffu, v.y, o);
            if (lane >= o) { v.x += ax; v.y += ay; }
        }
        if (lane == 31) wsum[grp][wir] = v;
        __syncthreads();
        #pragma unroll
        for (int k = 0; k < 3; k++)
            if (wir > k) { v.x += wsum[grp][k].x; v.y += wsum[grp][k].y; }

        float u = fmaxf(v.x * CXU, v.y * CYU);
        u = fminf(fmaxf(u, 0.5f), 2.0f);
        g_util[t * NUM_BINS + c] = u;
    }
    grid_bar(4 * GRID);

    // ---- Phase D: nodes (branchless 3x3 taps) ----
    for (int m = gid0; m < NUM_MOVABLE; m += NTH) {
        float nx = __ldg(pos + m), ny = __ldg(pos + m + NUM_NODES);
        float sx = __ldg(nszx + m), sy = __ldg(nszy + m);
        float xh = nx + sx, yh = ny + sy;

        int x0 = bin_of(nx);
        int y0 = bin_of(ny);

        float wy[3];
        int   yi[3];
        #pragma unroll
        for (int j = 0; j < 3; j++) {
            float by = (float)(y0 + j) * SB;
            wy[j] = fmaxf(fminf(by + SB, yh) - fmaxf(by, ny), 0.f);
            yi[j] = min(y0 + j, NUM_BINS - 1);
        }

        float acc = 0.f;
        #pragma unroll
        for (int k = 0; k < 3; k++) {
            float bx = (float)(x0 + k) * SB;
            float ox = fmaxf(fminf(bx + SB, xh) - fmaxf(bx, nx), 0.f);
            int row = min(x0 + k, NUM_BINS - 1) * NUM_BINS;
            float a2 = wy[0] * __ldg(&g_util[row + yi[0]])
                     + wy[1] * __ldg(&g_util[row + yi[1]])
                     + wy[2] * __ldg(&g_util[row + yi[2]]);
            acc += ox * a2;
        }
        out[m] = acc;
    }

    // ---- Final: arrive; block 0 waits for all and resets the counter ----
    __syncthreads();
    if (tid == 0) {
        atomicAdd(&g_bar, 1);
        if (bid == 0) {
            while (atomicAdd(&g_bar, 0) < 5 * GRID) __nanosleep(32);
            atomicExch(&g_bar, 0);    // clean state for next graph replay
        }
    }
}

extern "C" void kernel_launch(void* const* d_in, const int* in_sizes, int n_in,
                              void* d_out, int out_size) {
    const float* pos          = (const float*)d_in[0];
    const float* pin_pos      = (const float*)d_in[1];
    const float* node_size_x  = (const float*)d_in[2];
    const float* node_size_y  = (const float*)d_in[3];
    const float* net_weights  = (const float*)d_in[4];
    const int*   netpin_start = (const int*)d_in[5];
    const int*   flat_netpin  = (const int*)d_in[6];
    float* out = (float*)d_out;

    fused_kernel<<<GRID, BLK>>>(pos, pin_pos, node_size_x, node_size_y,
                                net_weights, netpin_start, flat_netpin, out);
}